// round 15
// baseline (speedup 1.0000x reference)
#include <cuda_runtime.h>
#include <cuda_fp16.h>
#include <cstdint>

#define BB 16
#define PP 2048
#define HB 2048
#define DB 1024

// ---- device scratch (static __device__ globals) ----
__device__ __half g_Eh[(size_t)BB * PP * HB];    // 128 MB  exp(sim)*mask, fp16
__device__ __half g_Qh[(size_t)BB * PP * DB];    //  64 MB  premise fp16
__device__ __half g_Kh[(size_t)BB * HB * DB];    //  64 MB  hypothesis fp16 [b,h,d] (K and V)
__device__ float g_psum[(size_t)BB * PP * 16];
__device__ int g_hlen[BB];
__device__ int g_plen[BB];

// ---- helpers ----
__device__ __forceinline__ uint32_t smem_u32(const void* p) {
    uint32_t a;
    asm("{ .reg .u64 t; cvta.to.shared.u64 t, %1; cvt.u32.u64 %0, t; }" : "=r"(a) : "l"(p));
    return a;
}

__device__ __forceinline__ void cp_async16(uint32_t dst, const void* src) {
    asm volatile("cp.async.cg.shared.global [%0], [%1], 16;" :: "r"(dst), "l"(src));
}

__device__ __forceinline__ void ldsm4(uint32_t& r0, uint32_t& r1, uint32_t& r2, uint32_t& r3,
                                      uint32_t addr) {
    asm volatile("ldmatrix.sync.aligned.m8n8.x4.shared.b16 {%0,%1,%2,%3}, [%4];"
                 : "=r"(r0), "=r"(r1), "=r"(r2), "=r"(r3) : "r"(addr));
}

__device__ __forceinline__ void ldsm4t(uint32_t& r0, uint32_t& r1, uint32_t& r2, uint32_t& r3,
                                       uint32_t addr) {
    asm volatile("ldmatrix.sync.aligned.m8n8.x4.trans.shared.b16 {%0,%1,%2,%3}, [%4];"
                 : "=r"(r0), "=r"(r1), "=r"(r2), "=r"(r3) : "r"(addr));
}

__device__ __forceinline__ void mma16(float c[4], uint32_t a0, uint32_t a1, uint32_t a2,
                                      uint32_t a3, uint32_t b0, uint32_t b1) {
    asm volatile(
        "mma.sync.aligned.m16n8k16.row.col.f32.f16.f16.f32 "
        "{%0,%1,%2,%3}, {%4,%5,%6,%7}, {%8,%9}, {%0,%1,%2,%3};\n"
        : "+f"(c[0]), "+f"(c[1]), "+f"(c[2]), "+f"(c[3])
        : "r"(a0), "r"(a1), "r"(a2), "r"(a3), "r"(b0), "r"(b1));
}

// ---------------------------------------------------------------------------
// prep kernels (mask-aware: fully dead rows written as zeros, no read)
// ---------------------------------------------------------------------------
__global__ __launch_bounds__(256) void len_k(const float* __restrict__ hmask,
                                             const float* __restrict__ pmask) {
    const int b = blockIdx.x, tid = threadIdx.x;
    float s1 = 0.0f, s2 = 0.0f;
    for (int i = tid; i < HB; i += 256) s1 += hmask[(size_t)b * HB + i];
    for (int i = tid; i < PP; i += 256) s2 += pmask[(size_t)b * PP + i];
    __shared__ float r1[256], r2[256];
    r1[tid] = s1; r2[tid] = s2;
    __syncthreads();
    for (int o = 128; o > 0; o >>= 1) {
        if (tid < o) { r1[tid] += r1[tid + o]; r2[tid] += r2[tid + o]; }
        __syncthreads();
    }
    if (tid == 0) {
        g_hlen[b] = (int)(r1[0] + 0.5f);
        g_plen[b] = (int)(r2[0] + 0.5f);
    }
}

template <int ISQ>
__global__ __launch_bounds__(256) void conv_fp32_fp16(const float4* __restrict__ in) {
    const int b = blockIdx.y;
    const int rlen = ISQ ? g_plen[b] : g_hlen[b];
    constexpr int n4 = (ISQ ? PP : HB) * (DB / 4);
    uint2* outp = (uint2*)(ISQ ? g_Qh : g_Kh) + (size_t)b * n4;
    const float4* inb = in + (size_t)b * n4;
    const int stride = gridDim.x * 256;
    for (int i = blockIdx.x * 256 + threadIdx.x; i < n4; i += stride) {
        int r = i >> 8;
        uint2 o;
        if (r < rlen) {
            float4 v = inb[i];
            __half2 lo = __floats2half2_rn(v.x, v.y);
            __half2 hi = __floats2half2_rn(v.z, v.w);
            o.x = *reinterpret_cast<uint32_t*>(&lo);
            o.y = *reinterpret_cast<uint32_t*>(&hi);
        } else {
            o.x = 0u; o.y = 0u;
        }
        outp[i] = o;
    }
}

// ---------------------------------------------------------------------------
// fp16 mma.sync GEMM. CTA tile 128x128, 8 warps (2m x 4n), warp tile 64x32.
// 2 CTAs/SM -> 4 warps/SMSP (tensor-pipe saturation). 32-half k-chunks,
// XOR-swizzled conflict-free smem, 4-stage cp.async. Mask-aware skipping.
// MODE 0: A=g_Qh, B=g_Kh k-major (K=1024). E=exp(acc/32)*hmask -> g_Eh, psum.
// MODE 1: A=g_Eh; B = V direct from g_Kh [h][d] via ldmatrix.trans.
//         K trunc to ceil32(hlen); rowsum folded into prologue.
// ---------------------------------------------------------------------------
#define OP_B 8192u
#define STAGE_B 16384u
#define NSTAGE 4
#define RS_OFF (NSTAGE * STAGE_B)
#define SMEM_BYTES (NSTAGE * STAGE_B + 512)    // 66048; x2 CTAs = 132KB/SM

template <int MODE>
__global__ __launch_bounds__(256, 2) void attn_gemm(const float* __restrict__ hmask,
                                                    const float* __restrict__ pmask,
                                                    float* __restrict__ outp) {
    constexpr int KD = MODE ? HB : DB;
    constexpr int S = KD / 32;

    extern __shared__ float smf[];
    const uint32_t sbase = smem_u32(smf);

    const int tid = threadIdx.x;
    const int x = blockIdx.x, y = blockIdx.y, b = blockIdx.z;
    const int lane = tid & 31, w = tid >> 5;
    const int wm = w >> 2, wn = w & 3;       // 2m x 4n warps, each 64x32
    const int g = lane >> 2, tg = lane & 3;

    const size_t growbase = (size_t)b * PP + (size_t)y * 128;

    int Send = S;
    if (MODE == 0) {
        if (x * 128 >= g_hlen[b] || y * 128 >= g_plen[b]) return;
    } else {
        if (y * 128 >= g_plen[b]) {
            if (tid < 128) {
                float4 z = make_float4(0.0f, 0.0f, 0.0f, 0.0f);
                float4* dst = (float4*)(outp + (growbase + tid) * DB + x * 128);
#pragma unroll
                for (int c = 0; c < 32; c++) dst[c] = z;
            }
            return;
        }
        Send = (g_hlen[b] + 31) >> 5;
    }

    const __half* Ab = (MODE ? g_Eh : g_Qh) + ((size_t)b * PP + (size_t)y * 128) * KD;
    const __half* Bb = g_Kh + (size_t)b * (size_t)(HB * DB)
                       + (MODE ? (size_t)(x * 128) : (size_t)x * 128 * DB);

    float acc[4][4][4];
#pragma unroll
    for (int mt = 0; mt < 4; mt++)
#pragma unroll
        for (int nt = 0; nt < 4; nt++)
#pragma unroll
            for (int i = 0; i < 4; i++) acc[mt][nt][i] = 0.0f;

    auto load_stage = [&](int s, int buf) {
        if (s < Send) {
            const int kc = s * 32;
            const uint32_t stb = sbase + (uint32_t)buf * STAGE_B;
            // A: 128 rows x 64B, swizzle c ^ ((r>>1)&3)
#pragma unroll
            for (int i = 0; i < 2; i++) {
                int idx = i * 256 + tid;          // 0..511
                int r = idx >> 2, c = idx & 3;
                uint32_t sw = (uint32_t)(c ^ ((r >> 1) & 3));
                cp_async16(stb + (uint32_t)r * 64 + sw * 16,
                           Ab + (size_t)r * KD + kc + c * 8);
            }
            if (MODE == 0) {
#pragma unroll
                for (int i = 0; i < 2; i++) {
                    int idx = i * 256 + tid;
                    int r = idx >> 2, c = idx & 3;
                    uint32_t sw = (uint32_t)(c ^ ((r >> 1) & 3));
                    cp_async16(stb + OP_B + (uint32_t)r * 64 + sw * 16,
                               Bb + (size_t)r * DB + kc + c * 8);
                }
            } else {
                // B: V rows kc..kc+31 x 256B, swizzle c16 ^ (r&7)
#pragma unroll
                for (int i = 0; i < 2; i++) {
                    int idx = i * 256 + tid;
                    int r = idx >> 4, c = idx & 15;
                    uint32_t sw = (uint32_t)(c ^ (r & 7));
                    cp_async16(stb + OP_B + (uint32_t)r * 256 + sw * 16,
                               Bb + (size_t)(kc + r) * DB + c * 8);
                }
            }
        }
        asm volatile("cp.async.commit_group;" ::: "memory");
    };

    load_stage(0, 0);
    load_stage(1, 1);
    load_stage(2, 2);

    if (MODE == 1 && tid < 128) {
        const float* ps = g_psum + (growbase + tid) * 16;
        float s16 = 0.0f;
#pragma unroll
        for (int j = 0; j < 16; j++) s16 += ps[j];
        *(float*)((char*)smf + RS_OFF + tid * 4) = s16;
    }

    // A ldmatrix offsets (swizzle folded; j toggles ^32)
    const int ra = wm * 64 + (lane & 15);
    const uint32_t a_c0 = (uint32_t)(((lane >> 4) ^ ((ra >> 1) & 3)) & 3);
    const uint32_t a_off0 = (uint32_t)ra * 64 + a_c0 * 16;
    // B MODE0: k-major n-rows (non-trans); warp covers 32 n-rows (2 ldsm per j)
    const int rb = wn * 32 + ((lane >> 4) << 3) + (lane & 7);
    const uint32_t b_c0 = (uint32_t)((((lane >> 3) & 1) ^ ((rb >> 1) & 3)) & 3);
    const uint32_t b_off0 = OP_B + (uint32_t)rb * 64 + b_c0 * 16;
    // B MODE1: trans; warp covers 32 d-cols = chunks wn*4 + {0..3}
    const uint32_t v_row = (uint32_t)((((lane >> 3) & 1) << 3) + (lane & 7));
    const uint32_t v_c0 = (uint32_t)(wn * 4 + (lane >> 4));
    const uint32_t v_key = (uint32_t)(lane & 7);
    const uint32_t v_base = OP_B + v_row * 256;

#pragma unroll 1
    for (int s = 0; s < Send; s++) {
        asm volatile("cp.async.wait_group 2;" ::: "memory");
        __syncthreads();
        load_stage(s + 3, (s + 3) & 3);

        const uint32_t stb = sbase + (uint32_t)(s & 3) * STAGE_B;
#pragma unroll
        for (int j = 0; j < 2; j++) {
            const uint32_t jx = (uint32_t)j << 5;
            uint32_t bf[4][2];
#pragma unroll
            for (int ntp = 0; ntp < 2; ntp++) {
                uint32_t q0, q1, q2, q3;
                if (MODE == 0) {
                    ldsm4(q0, q1, q2, q3, stb + ((b_off0 + (uint32_t)ntp * 1024) ^ jx));
                } else {
                    uint32_t c16 = (v_c0 + (uint32_t)ntp * 2) ^ v_key;
                    ldsm4t(q0, q1, q2, q3,
                           stb + v_base + (uint32_t)j * 4096 + c16 * 16);
                }
                bf[2 * ntp][0] = q0; bf[2 * ntp][1] = q1;
                bf[2 * ntp + 1][0] = q2; bf[2 * ntp + 1][1] = q3;
            }
#pragma unroll
            for (int mt = 0; mt < 4; mt++) {
                uint32_t a0, a1, a2, a3;
                ldsm4(a0, a1, a2, a3, stb + ((a_off0 + (uint32_t)mt * 1024) ^ jx));
#pragma unroll
                for (int nt = 0; nt < 4; nt++)
                    mma16(acc[mt][nt], a0, a1, a2, a3, bf[nt][0], bf[nt][1]);
            }
        }
    }

    // ---- epilogue ----
    __syncthreads();

    if (MODE == 0) {
        const float* hm = hmask + (size_t)b * HB + x * 128;
        float ps[4][2];
#pragma unroll
        for (int mt = 0; mt < 4; mt++) { ps[mt][0] = 0.0f; ps[mt][1] = 0.0f; }

#pragma unroll
        for (int mt = 0; mt < 4; mt++) {
            const int r0 = wm * 64 + mt * 16 + g;
#pragma unroll
            for (int nt = 0; nt < 4; nt++) {
                const int col = wn * 32 + nt * 8 + 2 * tg;
                float2 m = *(const float2*)(hm + col);
                float e0 = (m.x != 0.0f) ? __expf(acc[mt][nt][0] * 0.03125f) : 0.0f;
                float e1 = (m.y != 0.0f) ? __expf(acc[mt][nt][1] * 0.03125f) : 0.0f;
                float e2 = (m.x != 0.0f) ? __expf(acc[mt][nt][2] * 0.03125f) : 0.0f;
                float e3 = (m.y != 0.0f) ? __expf(acc[mt][nt][3] * 0.03125f) : 0.0f;
                __half2 h01 = __floats2half2_rn(e0, e1);
                __half2 h23 = __floats2half2_rn(e2, e3);
                *(__half2*)(g_Eh + (growbase + r0) * HB + x * 128 + col) = h01;
                *(__half2*)(g_Eh + (growbase + r0 + 8) * HB + x * 128 + col) = h23;
                float2 f01 = __half22float2(h01);
                float2 f23 = __half22float2(h23);
                ps[mt][0] += f01.x + f01.y;
                ps[mt][1] += f23.x + f23.y;
            }
        }
#pragma unroll
        for (int mt = 0; mt < 4; mt++)
#pragma unroll
            for (int h = 0; h < 2; h++) {
                float v = ps[mt][h];
                v += __shfl_xor_sync(0xFFFFFFFFu, v, 1);
                v += __shfl_xor_sync(0xFFFFFFFFu, v, 2);
                if (tg == 0) {
                    int rloc = wm * 64 + mt * 16 + g + h * 8;
                    smf[rloc * 4 + wn] = v;
                }
            }
        __syncthreads();
        if (tid < 128) {
            float s4 = smf[tid * 4 + 0] + smf[tid * 4 + 1]
                     + smf[tid * 4 + 2] + smf[tid * 4 + 3];
            g_psum[(growbase + tid) * 16 + x] = s4;
        }
    } else {
        const float* rs = (const float*)((const char*)smf + RS_OFF);
#pragma unroll
        for (int mt = 0; mt < 4; mt++) {
            const int r0 = wm * 64 + mt * 16 + g;
            const size_t grow0 = growbase + r0, grow1 = growbase + r0 + 8;
            const float pm0 = pmask[grow0], pm1 = pmask[grow1];
            const float s0 = (pm0 != 0.0f) ? pm0 / (rs[r0] + 1e-13f) : 0.0f;
            const float s1 = (pm1 != 0.0f) ? pm1 / (rs[r0 + 8] + 1e-13f) : 0.0f;
#pragma unroll
            for (int nt = 0; nt < 4; nt++) {
                const int col = x * 128 + wn * 32 + nt * 8 + 2 * tg;
                *(float2*)(outp + grow0 * DB + col) =
                    make_float2(acc[mt][nt][0] * s0, acc[mt][nt][1] * s0);
                *(float2*)(outp + grow1 * DB + col) =
                    make_float2(acc[mt][nt][2] * s1, acc[mt][nt][3] * s1);
            }
        }
    }
}

// ---------------------------------------------------------------------------
extern "C" void kernel_launch(void* const* d_in, const int* in_sizes, int n_in,
                              void* d_out, int out_size) {
    const float* Q     = (const float*)d_in[0];  // premise_batch    [B,P,D]
    const float* pmask = (const float*)d_in[1];  // premise_mask     [B,P]
    const float* HYP   = (const float*)d_in[2];  // hypothesis_batch [B,H,D]
    const float* hmask = (const float*)d_in[3];  // hypothesis_mask  [B,H]
    float* out = (float*)d_out;

    cudaFuncSetAttribute(attn_gemm<0>, cudaFuncAttributeMaxDynamicSharedMemorySize, SMEM_BYTES);
    cudaFuncSetAttribute(attn_gemm<1>, cudaFuncAttributeMaxDynamicSharedMemorySize, SMEM_BYTES);

    len_k<<<BB, 256>>>(hmask, pmask);
    conv_fp32_fp16<1><<<dim3(1024, BB), 256>>>((const float4*)Q);
    conv_fp32_fp16<0><<<dim3(1024, BB), 256>>>((const float4*)HYP);
    attn_gemm<0><<<dim3(16, 16, 16), 256, SMEM_BYTES>>>(hmask, nullptr, nullptr);
    attn_gemm<1><<<dim3(8, 16, 16), 256, SMEM_BYTES>>>(nullptr, pmask, out);
}

// round 16
// speedup vs baseline: 1.1716x; 1.1716x over previous
#include <cuda_runtime.h>
#include <cuda_fp16.h>
#include <cstdint>

#define BB 16
#define PP 2048
#define HB 2048
#define DB 1024

// ---- device scratch (static __device__ globals) ----
__device__ __half g_Eh[(size_t)BB * PP * HB];    // 128 MB  exp(sim)*mask, fp16
__device__ __half g_Qh[(size_t)BB * PP * DB];    //  64 MB  premise fp16
__device__ __half g_Kh[(size_t)BB * HB * DB];    //  64 MB  hypothesis fp16 [b,h,d] (K and V)
__device__ float g_psum[(size_t)BB * PP * 16];
__device__ int g_hlen[BB];
__device__ int g_plen[BB];

// ---- helpers ----
__device__ __forceinline__ uint32_t smem_u32(const void* p) {
    uint32_t a;
    asm("{ .reg .u64 t; cvta.to.shared.u64 t, %1; cvt.u32.u64 %0, t; }" : "=r"(a) : "l"(p));
    return a;
}

__device__ __forceinline__ void cp_async16(uint32_t dst, const void* src) {
    asm volatile("cp.async.cg.shared.global [%0], [%1], 16;" :: "r"(dst), "l"(src));
}

__device__ __forceinline__ void ldsm4(uint32_t& r0, uint32_t& r1, uint32_t& r2, uint32_t& r3,
                                      uint32_t addr) {
    asm volatile("ldmatrix.sync.aligned.m8n8.x4.shared.b16 {%0,%1,%2,%3}, [%4];"
                 : "=r"(r0), "=r"(r1), "=r"(r2), "=r"(r3) : "r"(addr));
}

__device__ __forceinline__ void ldsm4t(uint32_t& r0, uint32_t& r1, uint32_t& r2, uint32_t& r3,
                                       uint32_t addr) {
    asm volatile("ldmatrix.sync.aligned.m8n8.x4.trans.shared.b16 {%0,%1,%2,%3}, [%4];"
                 : "=r"(r0), "=r"(r1), "=r"(r2), "=r"(r3) : "r"(addr));
}

__device__ __forceinline__ void mma16(float c[4], uint32_t a0, uint32_t a1, uint32_t a2,
                                      uint32_t a3, uint32_t b0, uint32_t b1) {
    asm volatile(
        "mma.sync.aligned.m16n8k16.row.col.f32.f16.f16.f32 "
        "{%0,%1,%2,%3}, {%4,%5,%6,%7}, {%8,%9}, {%0,%1,%2,%3};\n"
        : "+f"(c[0]), "+f"(c[1]), "+f"(c[2]), "+f"(c[3])
        : "r"(a0), "r"(a1), "r"(a2), "r"(a3), "r"(b0), "r"(b1));
}

// ---------------------------------------------------------------------------
// prep kernels (mask-aware: fully dead rows written as zeros, no read)
// ---------------------------------------------------------------------------
__global__ __launch_bounds__(256) void len_k(const float* __restrict__ hmask,
                                             const float* __restrict__ pmask) {
    const int b = blockIdx.x, tid = threadIdx.x;
    float s1 = 0.0f, s2 = 0.0f;
    for (int i = tid; i < HB; i += 256) s1 += hmask[(size_t)b * HB + i];
    for (int i = tid; i < PP; i += 256) s2 += pmask[(size_t)b * PP + i];
    __shared__ float r1[256], r2[256];
    r1[tid] = s1; r2[tid] = s2;
    __syncthreads();
    for (int o = 128; o > 0; o >>= 1) {
        if (tid < o) { r1[tid] += r1[tid + o]; r2[tid] += r2[tid + o]; }
        __syncthreads();
    }
    if (tid == 0) {
        g_hlen[b] = (int)(r1[0] + 0.5f);
        g_plen[b] = (int)(r2[0] + 0.5f);
    }
}

template <int ISQ>
__global__ __launch_bounds__(256) void conv_fp32_fp16(const float4* __restrict__ in) {
    const int b = blockIdx.y;
    const int rlen = ISQ ? g_plen[b] : g_hlen[b];
    constexpr int n4 = (ISQ ? PP : HB) * (DB / 4);
    uint2* outp = (uint2*)(ISQ ? g_Qh : g_Kh) + (size_t)b * n4;
    const float4* inb = in + (size_t)b * n4;
    const int stride = gridDim.x * 256;
    for (int i = blockIdx.x * 256 + threadIdx.x; i < n4; i += stride) {
        int r = i >> 8;
        uint2 o;
        if (r < rlen) {
            float4 v = inb[i];
            __half2 lo = __floats2half2_rn(v.x, v.y);
            __half2 hi = __floats2half2_rn(v.z, v.w);
            o.x = *reinterpret_cast<uint32_t*>(&lo);
            o.y = *reinterpret_cast<uint32_t*>(&hi);
        } else {
            o.x = 0u; o.y = 0u;
        }
        outp[i] = o;
    }
}

// ---------------------------------------------------------------------------
// fp16 mma.sync GEMM. CTA tile 128x128, 4 warps (2x2), warp tile 64x64.
// 32-half k-chunks, XOR-swizzled conflict-free smem, 4-stage cp.async,
// 2 CTAs/SM. Software-pipelined fragments: ldsm for phase p+1 issued while
// MMAs of phase p run (double-buffered fragment regs), so each warp's 64-MMA
// trains issue without short-scoreboard stalls. Mask-aware tile skipping.
// MODE 0: A=g_Qh, B=g_Kh k-major (K=1024). E=exp(acc/32)*hmask -> g_Eh, psum.
// MODE 1: A=g_Eh; B = V direct from g_Kh [h][d] via ldmatrix.trans.
//         K trunc to ceil32(hlen); rowsum folded into prologue.
// ---------------------------------------------------------------------------
#define OP_B 8192u
#define STAGE_B 16384u
#define NSTAGE 4
#define RS_OFF (NSTAGE * STAGE_B)
#define SMEM_BYTES (NSTAGE * STAGE_B + 512)    // 66048; x2 CTAs = 132KB/SM

template <int MODE>
__global__ __launch_bounds__(128, 2) void attn_gemm(const float* __restrict__ hmask,
                                                    const float* __restrict__ pmask,
                                                    float* __restrict__ outp) {
    constexpr int KD = MODE ? HB : DB;
    constexpr int S = KD / 32;

    extern __shared__ float smf[];
    const uint32_t sbase = smem_u32(smf);

    const int tid = threadIdx.x;
    const int x = blockIdx.x, y = blockIdx.y, b = blockIdx.z;
    const int lane = tid & 31, w = tid >> 5;
    const int wm = w >> 1, wn = w & 1;       // 2x2 warps, each 64x64
    const int g = lane >> 2, tg = lane & 3;

    const size_t growbase = (size_t)b * PP + (size_t)y * 128;

    int Send = S;
    if (MODE == 0) {
        if (x * 128 >= g_hlen[b] || y * 128 >= g_plen[b]) return;
    } else {
        if (y * 128 >= g_plen[b]) {
            float4 z = make_float4(0.0f, 0.0f, 0.0f, 0.0f);
            float4* dst = (float4*)(outp + (growbase + tid) * DB + x * 128);
#pragma unroll
            for (int c = 0; c < 32; c++) dst[c] = z;
            return;
        }
        Send = (g_hlen[b] + 31) >> 5;
    }

    const __half* Ab = (MODE ? g_Eh : g_Qh) + ((size_t)b * PP + (size_t)y * 128) * KD;
    const __half* Bb = g_Kh + (size_t)b * (size_t)(HB * DB)
                       + (MODE ? (size_t)(x * 128) : (size_t)x * 128 * DB);

    float acc[4][8][4];
#pragma unroll
    for (int mt = 0; mt < 4; mt++)
#pragma unroll
        for (int nt = 0; nt < 8; nt++)
#pragma unroll
            for (int i = 0; i < 4; i++) acc[mt][nt][i] = 0.0f;

    auto load_stage = [&](int s, int buf) {
        if (s < Send) {
            const int kc = s * 32;
            const uint32_t stb = sbase + (uint32_t)buf * STAGE_B;
#pragma unroll
            for (int i = 0; i < 4; i++) {
                int idx = i * 128 + tid;          // 0..511
                int r = idx >> 2, c = idx & 3;
                uint32_t sw = (uint32_t)(c ^ ((r >> 1) & 3));
                cp_async16(stb + (uint32_t)r * 64 + sw * 16,
                           Ab + (size_t)r * KD + kc + c * 8);
            }
            if (MODE == 0) {
#pragma unroll
                for (int i = 0; i < 4; i++) {
                    int idx = i * 128 + tid;
                    int r = idx >> 2, c = idx & 3;
                    uint32_t sw = (uint32_t)(c ^ ((r >> 1) & 3));
                    cp_async16(stb + OP_B + (uint32_t)r * 64 + sw * 16,
                               Bb + (size_t)r * DB + kc + c * 8);
                }
            } else {
#pragma unroll
                for (int i = 0; i < 4; i++) {
                    int idx = i * 128 + tid;
                    int r = idx >> 4, c = idx & 15;
                    uint32_t sw = (uint32_t)(c ^ (r & 7));
                    cp_async16(stb + OP_B + (uint32_t)r * 256 + sw * 16,
                               Bb + (size_t)(kc + r) * DB + c * 8);
                }
            }
        }
        asm volatile("cp.async.commit_group;" ::: "memory");
    };

    // fragment addressing
    const int ra = wm * 64 + (lane & 15);
    const uint32_t a_c0 = (uint32_t)(((lane >> 4) ^ ((ra >> 1) & 3)) & 3);
    const uint32_t a_off0 = (uint32_t)ra * 64 + a_c0 * 16;
    const int rb = wn * 64 + ((lane >> 4) << 3) + (lane & 7);
    const uint32_t b_c0 = (uint32_t)((((lane >> 3) & 1) ^ ((rb >> 1) & 3)) & 3);
    const uint32_t b_off0 = OP_B + (uint32_t)rb * 64 + b_c0 * 16;
    const uint32_t v_row = (uint32_t)((((lane >> 3) & 1) << 3) + (lane & 7));
    const uint32_t v_c0 = (uint32_t)(wn * 8 + (lane >> 4));
    const uint32_t v_key = (uint32_t)(lane & 7);
    const uint32_t v_base = OP_B + v_row * 256;

    uint32_t fa[2][4][4];     // [phase buf][mt][frag]
    uint32_t fb[2][8][2];     // [phase buf][nt][frag]

    auto frag_load = [&](int pb, int sidx, int j) {
        const uint32_t stb = sbase + (uint32_t)(sidx & 3) * STAGE_B;
        const uint32_t jx = (uint32_t)j << 5;
#pragma unroll
        for (int ntp = 0; ntp < 4; ntp++) {
            uint32_t q0, q1, q2, q3;
            if (MODE == 0) {
                ldsm4(q0, q1, q2, q3, stb + ((b_off0 + (uint32_t)ntp * 1024) ^ jx));
            } else {
                uint32_t c16 = (v_c0 + (uint32_t)ntp * 2) ^ v_key;
                ldsm4t(q0, q1, q2, q3,
                       stb + v_base + (uint32_t)j * 4096 + c16 * 16);
            }
            fb[pb][2 * ntp][0] = q0; fb[pb][2 * ntp][1] = q1;
            fb[pb][2 * ntp + 1][0] = q2; fb[pb][2 * ntp + 1][1] = q3;
        }
#pragma unroll
        for (int mt = 0; mt < 4; mt++)
            ldsm4(fa[pb][mt][0], fa[pb][mt][1], fa[pb][mt][2], fa[pb][mt][3],
                  stb + ((a_off0 + (uint32_t)mt * 1024) ^ jx));
    };

    auto mma_phase = [&](int pb) {
#pragma unroll
        for (int mt = 0; mt < 4; mt++)
#pragma unroll
            for (int nt = 0; nt < 8; nt++)
                mma16(acc[mt][nt], fa[pb][mt][0], fa[pb][mt][1],
                      fa[pb][mt][2], fa[pb][mt][3], fb[pb][nt][0], fb[pb][nt][1]);
    };

    load_stage(0, 0);
    load_stage(1, 1);
    load_stage(2, 2);

    // PV: fold rowsum reduction into the prologue (overlaps with cp.async)
    if (MODE == 1) {
        const float* ps = g_psum + (growbase + tid) * 16;
        float s16 = 0.0f;
#pragma unroll
        for (int j = 0; j < 16; j++) s16 += ps[j];
        *(float*)((char*)smf + RS_OFF + tid * 4) = s16;
    }

    asm volatile("cp.async.wait_group 2;" ::: "memory");
    __syncthreads();
    frag_load(0, 0, 0);                          // phase (0,0) -> buf0

#pragma unroll 1
    for (int s = 0; s < Send; s++) {
        load_stage(s + 3, (s + 3) & 3);
        frag_load(1, s, 1);                      // phase (s,1) -> buf1 (stage s)
        mma_phase(0);                            // phase (s,0)
        asm volatile("cp.async.wait_group 2;" ::: "memory");
        __syncthreads();                         // stage s+1 visible; WAR gate
        if (s + 1 < Send)
            frag_load(0, s + 1, 0);              // phase (s+1,0) -> buf0
        mma_phase(1);                            // phase (s,1)
    }

    // ---- epilogue ----
    __syncthreads();

    if (MODE == 0) {
        const float* hm = hmask + (size_t)b * HB + x * 128;
        float ps[4][2];
#pragma unroll
        for (int mt = 0; mt < 4; mt++) { ps[mt][0] = 0.0f; ps[mt][1] = 0.0f; }

#pragma unroll
        for (int mt = 0; mt < 4; mt++) {
            const int r0 = wm * 64 + mt * 16 + g;
#pragma unroll
            for (int nt = 0; nt < 8; nt++) {
                const int col = wn * 64 + nt * 8 + 2 * tg;
                float2 m = *(const float2*)(hm + col);
                float e0 = (m.x != 0.0f) ? __expf(acc[mt][nt][0] * 0.03125f) : 0.0f;
                float e1 = (m.y != 0.0f) ? __expf(acc[mt][nt][1] * 0.03125f) : 0.0f;
                float e2 = (m.x != 0.0f) ? __expf(acc[mt][nt][2] * 0.03125f) : 0.0f;
                float e3 = (m.y != 0.0f) ? __expf(acc[mt][nt][3] * 0.03125f) : 0.0f;
                __half2 h01 = __floats2half2_rn(e0, e1);
                __half2 h23 = __floats2half2_rn(e2, e3);
                *(__half2*)(g_Eh + (growbase + r0) * HB + x * 128 + col) = h01;
                *(__half2*)(g_Eh + (growbase + r0 + 8) * HB + x * 128 + col) = h23;
                float2 f01 = __half22float2(h01);
                float2 f23 = __half22float2(h23);
                ps[mt][0] += f01.x + f01.y;
                ps[mt][1] += f23.x + f23.y;
            }
        }
#pragma unroll
        for (int mt = 0; mt < 4; mt++)
#pragma unroll
            for (int h = 0; h < 2; h++) {
                float v = ps[mt][h];
                v += __shfl_xor_sync(0xFFFFFFFFu, v, 1);
                v += __shfl_xor_sync(0xFFFFFFFFu, v, 2);
                if (tg == 0) {
                    int rloc = wm * 64 + mt * 16 + g + h * 8;
                    smf[rloc * 2 + wn] = v;
                }
            }
        __syncthreads();
        if (tid < 128) {
            float s2 = smf[tid * 2 + 0] + smf[tid * 2 + 1];
            g_psum[(growbase + tid) * 16 + x] = s2;
        }
    } else {
        const float* rs = (const float*)((const char*)smf + RS_OFF);
#pragma unroll
        for (int mt = 0; mt < 4; mt++) {
            const int r0 = wm * 64 + mt * 16 + g;
            const size_t grow0 = growbase + r0, grow1 = growbase + r0 + 8;
            const float pm0 = pmask[grow0], pm1 = pmask[grow1];
            const float s0 = (pm0 != 0.0f) ? pm0 / (rs[r0] + 1e-13f) : 0.0f;
            const float s1 = (pm1 != 0.0f) ? pm1 / (rs[r0 + 8] + 1e-13f) : 0.0f;
#pragma unroll
            for (int nt = 0; nt < 8; nt++) {
                const int col = x * 128 + wn * 64 + nt * 8 + 2 * tg;
                *(float2*)(outp + grow0 * DB + col) =
                    make_float2(acc[mt][nt][0] * s0, acc[mt][nt][1] * s0);
                *(float2*)(outp + grow1 * DB + col) =
                    make_float2(acc[mt][nt][2] * s1, acc[mt][nt][3] * s1);
            }
        }
    }
}

// ---------------------------------------------------------------------------
extern "C" void kernel_launch(void* const* d_in, const int* in_sizes, int n_in,
                              void* d_out, int out_size) {
    const float* Q     = (const float*)d_in[0];  // premise_batch    [B,P,D]
    const float* pmask = (const float*)d_in[1];  // premise_mask     [B,P]
    const float* HYP   = (const float*)d_in[2];  // hypothesis_batch [B,H,D]
    const float* hmask = (const float*)d_in[3];  // hypothesis_mask  [B,H]
    float* out = (float*)d_out;

    cudaFuncSetAttribute(attn_gemm<0>, cudaFuncAttributeMaxDynamicSharedMemorySize, SMEM_BYTES);
    cudaFuncSetAttribute(attn_gemm<1>, cudaFuncAttributeMaxDynamicSharedMemorySize, SMEM_BYTES);

    len_k<<<BB, 256>>>(hmask, pmask);
    conv_fp32_fp16<1><<<dim3(1024, BB), 256>>>((const float4*)Q);
    conv_fp32_fp16<0><<<dim3(1024, BB), 256>>>((const float4*)HYP);
    attn_gemm<0><<<dim3(16, 16, 16), 128, SMEM_BYTES>>>(hmask, nullptr, nullptr);
    attn_gemm<1><<<dim3(8, 16, 16), 128, SMEM_BYTES>>>(nullptr, pmask, out);
}

// round 17
// speedup vs baseline: 1.1786x; 1.0060x over previous
#include <cuda_runtime.h>
#include <cuda_fp16.h>
#include <cstdint>

#define BB 16
#define PP 2048
#define HB 2048
#define DB 1024

// ---- device scratch (static __device__ globals) ----
__device__ __half g_Eh[(size_t)BB * PP * HB];    // 128 MB  exp(sim)*mask, fp16
__device__ __half g_Qh[(size_t)BB * PP * DB];    //  64 MB  premise fp16
__device__ __half g_Kh[(size_t)BB * HB * DB];    //  64 MB  hypothesis fp16 [b,h,d] (K and V)
__device__ float g_psum[(size_t)BB * PP * 16];
__device__ int g_hlen[BB];
__device__ int g_plen[BB];

// ---- helpers ----
__device__ __forceinline__ uint32_t smem_u32(const void* p) {
    uint32_t a;
    asm("{ .reg .u64 t; cvta.to.shared.u64 t, %1; cvt.u32.u64 %0, t; }" : "=r"(a) : "l"(p));
    return a;
}

__device__ __forceinline__ void cp_async16(uint32_t dst, const void* src) {
    asm volatile("cp.async.cg.shared.global [%0], [%1], 16;" :: "r"(dst), "l"(src));
}

__device__ __forceinline__ void ldsm4(uint32_t& r0, uint32_t& r1, uint32_t& r2, uint32_t& r3,
                                      uint32_t addr) {
    asm volatile("ldmatrix.sync.aligned.m8n8.x4.shared.b16 {%0,%1,%2,%3}, [%4];"
                 : "=r"(r0), "=r"(r1), "=r"(r2), "=r"(r3) : "r"(addr));
}

__device__ __forceinline__ void ldsm4t(uint32_t& r0, uint32_t& r1, uint32_t& r2, uint32_t& r3,
                                       uint32_t addr) {
    asm volatile("ldmatrix.sync.aligned.m8n8.x4.trans.shared.b16 {%0,%1,%2,%3}, [%4];"
                 : "=r"(r0), "=r"(r1), "=r"(r2), "=r"(r3) : "r"(addr));
}

__device__ __forceinline__ void mma16(float c[4], uint32_t a0, uint32_t a1, uint32_t a2,
                                      uint32_t a3, uint32_t b0, uint32_t b1) {
    asm volatile(
        "mma.sync.aligned.m16n8k16.row.col.f32.f16.f16.f32 "
        "{%0,%1,%2,%3}, {%4,%5,%6,%7}, {%8,%9}, {%0,%1,%2,%3};\n"
        : "+f"(c[0]), "+f"(c[1]), "+f"(c[2]), "+f"(c[3])
        : "r"(a0), "r"(a1), "r"(a2), "r"(a3), "r"(b0), "r"(b1));
}

// ---------------------------------------------------------------------------
// prep kernels (mask-aware: fully dead rows written as zeros, no read)
// ---------------------------------------------------------------------------
__global__ __launch_bounds__(256) void len_k(const float* __restrict__ hmask,
                                             const float* __restrict__ pmask) {
    const int b = blockIdx.x, tid = threadIdx.x;
    float s1 = 0.0f, s2 = 0.0f;
    for (int i = tid; i < HB; i += 256) s1 += hmask[(size_t)b * HB + i];
    for (int i = tid; i < PP; i += 256) s2 += pmask[(size_t)b * PP + i];
    __shared__ float r1[256], r2[256];
    r1[tid] = s1; r2[tid] = s2;
    __syncthreads();
    for (int o = 128; o > 0; o >>= 1) {
        if (tid < o) { r1[tid] += r1[tid + o]; r2[tid] += r2[tid + o]; }
        __syncthreads();
    }
    if (tid == 0) {
        g_hlen[b] = (int)(r1[0] + 0.5f);
        g_plen[b] = (int)(r2[0] + 0.5f);
    }
}

// single launch converts both premise (z=0) and hypothesis (z=1)
__global__ __launch_bounds__(256) void conv_all(const float4* __restrict__ Q,
                                                const float4* __restrict__ HYP) {
    const int b = blockIdx.y;
    const int isq = (blockIdx.z == 0);
    const int rlen = isq ? g_plen[b] : g_hlen[b];
    const int n4 = (isq ? PP : HB) * (DB / 4);
    uint2* outp = (uint2*)(isq ? g_Qh : g_Kh) + (size_t)b * n4;
    const float4* inb = (isq ? Q : HYP) + (size_t)b * n4;
    const int stride = gridDim.x * 256;
    for (int i = blockIdx.x * 256 + threadIdx.x; i < n4; i += stride) {
        int r = i >> 8;
        uint2 o;
        if (r < rlen) {
            float4 v = inb[i];
            __half2 lo = __floats2half2_rn(v.x, v.y);
            __half2 hi = __floats2half2_rn(v.z, v.w);
            o.x = *reinterpret_cast<uint32_t*>(&lo);
            o.y = *reinterpret_cast<uint32_t*>(&hi);
        } else {
            o.x = 0u; o.y = 0u;
        }
        outp[i] = o;
    }
}

// ---------------------------------------------------------------------------
// fp16 mma.sync GEMM. CTA tile 128x128, 4 warps (2x2), warp tile 64x64.
// 32-half k-chunks, XOR-swizzled conflict-free smem, 5-stage cp.async,
// 2 CTAs/SM. Software-pipelined double-buffered fragments.
// MODE 0: A=g_Qh, B=g_Kh k-major (K=1024). E=exp(acc/32)*hmask -> g_Eh, psum.
// MODE 1: A=g_Eh; B = V direct from g_Kh [h][d] via ldmatrix.trans.
//         K trunc to ceil32(hlen); rowsum folded into prologue.
// ---------------------------------------------------------------------------
#define OP_B 8192u
#define STAGE_B 16384u
#define NSTAGE 5
#define RS_OFF (NSTAGE * STAGE_B)
#define SMEM_BYTES (NSTAGE * STAGE_B + 512)    // 82432; x2 CTAs = 165KB/SM

template <int MODE>
__global__ __launch_bounds__(128, 2) void attn_gemm(const float* __restrict__ hmask,
                                                    const float* __restrict__ pmask,
                                                    float* __restrict__ outp) {
    constexpr int KD = MODE ? HB : DB;
    constexpr int S = KD / 32;

    extern __shared__ float smf[];
    const uint32_t sbase = smem_u32(smf);

    const int tid = threadIdx.x;
    const int x = blockIdx.x, y = blockIdx.y, b = blockIdx.z;
    const int lane = tid & 31, w = tid >> 5;
    const int wm = w >> 1, wn = w & 1;       // 2x2 warps, each 64x64
    const int g = lane >> 2, tg = lane & 3;

    const size_t growbase = (size_t)b * PP + (size_t)y * 128;

    int Send = S;
    if (MODE == 0) {
        if (x * 128 >= g_hlen[b] || y * 128 >= g_plen[b]) return;
    } else {
        if (y * 128 >= g_plen[b]) {
            float4 z = make_float4(0.0f, 0.0f, 0.0f, 0.0f);
            float4* dst = (float4*)(outp + (growbase + tid) * DB + x * 128);
#pragma unroll
            for (int c = 0; c < 32; c++) dst[c] = z;
            return;
        }
        Send = (g_hlen[b] + 31) >> 5;
    }

    const __half* Ab = (MODE ? g_Eh : g_Qh) + ((size_t)b * PP + (size_t)y * 128) * KD;
    const __half* Bb = g_Kh + (size_t)b * (size_t)(HB * DB)
                       + (MODE ? (size_t)(x * 128) : (size_t)x * 128 * DB);

    float acc[4][8][4];
#pragma unroll
    for (int mt = 0; mt < 4; mt++)
#pragma unroll
        for (int nt = 0; nt < 8; nt++)
#pragma unroll
            for (int i = 0; i < 4; i++) acc[mt][nt][i] = 0.0f;

    auto load_stage = [&](int s, int buf) {
        if (s < Send) {
            const int kc = s * 32;
            const uint32_t stb = sbase + (uint32_t)buf * STAGE_B;
#pragma unroll
            for (int i = 0; i < 4; i++) {
                int idx = i * 128 + tid;          // 0..511
                int r = idx >> 2, c = idx & 3;
                uint32_t sw = (uint32_t)(c ^ ((r >> 1) & 3));
                cp_async16(stb + (uint32_t)r * 64 + sw * 16,
                           Ab + (size_t)r * KD + kc + c * 8);
            }
            if (MODE == 0) {
#pragma unroll
                for (int i = 0; i < 4; i++) {
                    int idx = i * 128 + tid;
                    int r = idx >> 2, c = idx & 3;
                    uint32_t sw = (uint32_t)(c ^ ((r >> 1) & 3));
                    cp_async16(stb + OP_B + (uint32_t)r * 64 + sw * 16,
                               Bb + (size_t)r * DB + kc + c * 8);
                }
            } else {
#pragma unroll
                for (int i = 0; i < 4; i++) {
                    int idx = i * 128 + tid;
                    int r = idx >> 4, c = idx & 15;
                    uint32_t sw = (uint32_t)(c ^ (r & 7));
                    cp_async16(stb + OP_B + (uint32_t)r * 256 + sw * 16,
                               Bb + (size_t)(kc + r) * DB + c * 8);
                }
            }
        }
        asm volatile("cp.async.commit_group;" ::: "memory");
    };

    // fragment addressing
    const int ra = wm * 64 + (lane & 15);
    const uint32_t a_c0 = (uint32_t)(((lane >> 4) ^ ((ra >> 1) & 3)) & 3);
    const uint32_t a_off0 = (uint32_t)ra * 64 + a_c0 * 16;
    const int rb = wn * 64 + ((lane >> 4) << 3) + (lane & 7);
    const uint32_t b_c0 = (uint32_t)((((lane >> 3) & 1) ^ ((rb >> 1) & 3)) & 3);
    const uint32_t b_off0 = OP_B + (uint32_t)rb * 64 + b_c0 * 16;
    const uint32_t v_row = (uint32_t)((((lane >> 3) & 1) << 3) + (lane & 7));
    const uint32_t v_c0 = (uint32_t)(wn * 8 + (lane >> 4));
    const uint32_t v_key = (uint32_t)(lane & 7);
    const uint32_t v_base = OP_B + v_row * 256;

    uint32_t fa[2][4][4];     // [phase buf][mt][frag]
    uint32_t fb[2][8][2];     // [phase buf][nt][frag]

    auto frag_load = [&](int pb, int sbuf, int j) {
        const uint32_t stb = sbase + (uint32_t)sbuf * STAGE_B;
        const uint32_t jx = (uint32_t)j << 5;
#pragma unroll
        for (int ntp = 0; ntp < 4; ntp++) {
            uint32_t q0, q1, q2, q3;
            if (MODE == 0) {
                ldsm4(q0, q1, q2, q3, stb + ((b_off0 + (uint32_t)ntp * 1024) ^ jx));
            } else {
                uint32_t c16 = (v_c0 + (uint32_t)ntp * 2) ^ v_key;
                ldsm4t(q0, q1, q2, q3,
                       stb + v_base + (uint32_t)j * 4096 + c16 * 16);
            }
            fb[pb][2 * ntp][0] = q0; fb[pb][2 * ntp][1] = q1;
            fb[pb][2 * ntp + 1][0] = q2; fb[pb][2 * ntp + 1][1] = q3;
        }
#pragma unroll
        for (int mt = 0; mt < 4; mt++)
            ldsm4(fa[pb][mt][0], fa[pb][mt][1], fa[pb][mt][2], fa[pb][mt][3],
                  stb + ((a_off0 + (uint32_t)mt * 1024) ^ jx));
    };

    auto mma_phase = [&](int pb) {
#pragma unroll
        for (int mt = 0; mt < 4; mt++)
#pragma unroll
            for (int nt = 0; nt < 8; nt++)
                mma16(acc[mt][nt], fa[pb][mt][0], fa[pb][mt][1],
                      fa[pb][mt][2], fa[pb][mt][3], fb[pb][nt][0], fb[pb][nt][1]);
    };

    load_stage(0, 0);
    load_stage(1, 1);
    load_stage(2, 2);
    load_stage(3, 3);

    // PV: fold rowsum reduction into the prologue (overlaps with cp.async)
    if (MODE == 1) {
        const float* ps = g_psum + (growbase + tid) * 16;
        float s16 = 0.0f;
#pragma unroll
        for (int j = 0; j < 16; j++) s16 += ps[j];
        *(float*)((char*)smf + RS_OFF + tid * 4) = s16;
    }

    asm volatile("cp.async.wait_group 3;" ::: "memory");
    __syncthreads();
    frag_load(0, 0, 0);                          // phase (0,0) -> buf0

    int cb = 0;                                  // stage buffer of chunk s
    int lb = 4;                                  // stage buffer for chunk s+4
#pragma unroll 1
    for (int s = 0; s < Send; s++) {
        frag_load(1, cb, 1);                     // phase (s,1) -> buf1 (ldsm first)
        load_stage(s + 4, lb);
        mma_phase(0);                            // phase (s,0)
        asm volatile("cp.async.wait_group 3;" ::: "memory");
        __syncthreads();                         // stage s+1 visible; WAR gate
        const int nb = (cb == 4) ? 0 : cb + 1;
        if (s + 1 < Send)
            frag_load(0, nb, 0);                 // phase (s+1,0) -> buf0
        mma_phase(1);                            // phase (s,1)
        cb = nb;
        lb = (lb == 4) ? 0 : lb + 1;
    }

    // ---- epilogue ----
    __syncthreads();

    if (MODE == 0) {
        const float* hm = hmask + (size_t)b * HB + x * 128;
        float ps[4][2];
#pragma unroll
        for (int mt = 0; mt < 4; mt++) { ps[mt][0] = 0.0f; ps[mt][1] = 0.0f; }

#pragma unroll
        for (int mt = 0; mt < 4; mt++) {
            const int r0 = wm * 64 + mt * 16 + g;
#pragma unroll
            for (int nt = 0; nt < 8; nt++) {
                const int col = wn * 64 + nt * 8 + 2 * tg;
                float2 m = *(const float2*)(hm + col);
                float e0 = (m.x != 0.0f) ? __expf(acc[mt][nt][0] * 0.03125f) : 0.0f;
                float e1 = (m.y != 0.0f) ? __expf(acc[mt][nt][1] * 0.03125f) : 0.0f;
                float e2 = (m.x != 0.0f) ? __expf(acc[mt][nt][2] * 0.03125f) : 0.0f;
                float e3 = (m.y != 0.0f) ? __expf(acc[mt][nt][3] * 0.03125f) : 0.0f;
                __half2 h01 = __floats2half2_rn(e0, e1);
                __half2 h23 = __floats2half2_rn(e2, e3);
                *(__half2*)(g_Eh + (growbase + r0) * HB + x * 128 + col) = h01;
                *(__half2*)(g_Eh + (growbase + r0 + 8) * HB + x * 128 + col) = h23;
                float2 f01 = __half22float2(h01);
                float2 f23 = __half22float2(h23);
                ps[mt][0] += f01.x + f01.y;
                ps[mt][1] += f23.x + f23.y;
            }
        }
#pragma unroll
        for (int mt = 0; mt < 4; mt++)
#pragma unroll
            for (int h = 0; h < 2; h++) {
                float v = ps[mt][h];
                v += __shfl_xor_sync(0xFFFFFFFFu, v, 1);
                v += __shfl_xor_sync(0xFFFFFFFFu, v, 2);
                if (tg == 0) {
                    int rloc = wm * 64 + mt * 16 + g + h * 8;
                    smf[rloc * 2 + wn] = v;
                }
            }
        __syncthreads();
        if (tid < 128) {
            float s2 = smf[tid * 2 + 0] + smf[tid * 2 + 1];
            g_psum[(growbase + tid) * 16 + x] = s2;
        }
    } else {
        const float* rs = (const float*)((const char*)smf + RS_OFF);
#pragma unroll
        for (int mt = 0; mt < 4; mt++) {
            const int r0 = wm * 64 + mt * 16 + g;
            const size_t grow0 = growbase + r0, grow1 = growbase + r0 + 8;
            const float pm0 = pmask[grow0], pm1 = pmask[grow1];
            const float s0 = (pm0 != 0.0f) ? pm0 / (rs[r0] + 1e-13f) : 0.0f;
            const float s1 = (pm1 != 0.0f) ? pm1 / (rs[r0 + 8] + 1e-13f) : 0.0f;
#pragma unroll
            for (int nt = 0; nt < 8; nt++) {
                const int col = x * 128 + wn * 64 + nt * 8 + 2 * tg;
                *(float2*)(outp + grow0 * DB + col) =
                    make_float2(acc[mt][nt][0] * s0, acc[mt][nt][1] * s0);
                *(float2*)(outp + grow1 * DB + col) =
                    make_float2(acc[mt][nt][2] * s1, acc[mt][nt][3] * s1);
            }
        }
    }
}

// ---------------------------------------------------------------------------
extern "C" void kernel_launch(void* const* d_in, const int* in_sizes, int n_in,
                              void* d_out, int out_size) {
    const float* Q     = (const float*)d_in[0];  // premise_batch    [B,P,D]
    const float* pmask = (const float*)d_in[1];  // premise_mask     [B,P]
    const float* HYP   = (const float*)d_in[2];  // hypothesis_batch [B,H,D]
    const float* hmask = (const float*)d_in[3];  // hypothesis_mask  [B,H]
    float* out = (float*)d_out;

    cudaFuncSetAttribute(attn_gemm<0>, cudaFuncAttributeMaxDynamicSharedMemorySize, SMEM_BYTES);
    cudaFuncSetAttribute(attn_gemm<1>, cudaFuncAttributeMaxDynamicSharedMemorySize, SMEM_BYTES);

    len_k<<<BB, 256>>>(hmask, pmask);
    conv_all<<<dim3(512, BB, 2), 256>>>((const float4*)Q, (const float4*)HYP);
    attn_gemm<0><<<dim3(16, 16, 16), 128, SMEM_BYTES>>>(hmask, nullptr, nullptr);
    attn_gemm<1><<<dim3(8, 16, 16), 128, SMEM_BYTES>>>(nullptr, pmask, out);
}